// round 17
// baseline (speedup 1.0000x reference)
#include <cuda_runtime.h>

#define NUM_CAT   16
#define NUM_ATTR  144
#define NUM_NUM   128
#define N_ARY     32
#define NUM_SEG   100000
#define N_ROWS    1000000

#define GRID_SZ     888            // 148 SMs x 6 blocks guaranteed resident
#define SCAT_TILES  31250          // 32 rows per tile
#define GATH_TILES  7813           // 128 rows per tile (tail-guarded)

// Scratch (device globals — no allocation allowed in kernel_launch)
__device__ __align__(16) float g_agg[NUM_SEG * N_ARY];   // 12.8 MB, L2-resident; slot = output rank
__device__ int   g_catidx[N_ROWS];                        // compact per-row segment id
__device__ __align__(16) float g_conf[N_ARY];             // conf by output rank
__device__ int   g_cols_rank[N_ARY];                      // rank k -> numeric col (0..127)
__device__ int   g_catcol;
__device__ unsigned g_bar;                                // monotonic ticket barrier

// Grid barrier: monotonic tickets, no reset, replay-safe. Barrier event k owns
// tickets [k*G,(k+1)*G); a block exits when the count reaches (t/G+1)*G. Fast
// blocks entering the next barrier only push the count higher, so spinners
// never miss the release.
__device__ __forceinline__ void grid_bar() {
    __syncthreads();
    if (threadIdx.x == 0) {
        __threadfence();                               // order REDG/STG before arrive
        unsigned t = atomicAdd(&g_bar, 1u);
        unsigned tgt = (t / GRID_SZ + 1u) * GRID_SZ;
        while (*(volatile unsigned*)&g_bar < tgt) { }
        __threadfence();
    }
    __syncthreads();
}

// ---------------------------------------------------------------------------
// ONE persistent kernel: phase0 (zero || setup) -> bar -> scatter -> bar -> gather
// ---------------------------------------------------------------------------
__global__ void __launch_bounds__(256, 6)
k_fused(const float* __restrict__ inputs,
        const int*   __restrict__ idx_inputs,
        const float* __restrict__ cat_mask,
        const float* __restrict__ num_mask,
        float*       __restrict__ out) {
    const unsigned FULL = 0xffffffffu;
    __shared__ __align__(16) float s_row[8][4][132];   // 16.9 KB scatter staging
    __shared__ int    s_cols[N_ARY];
    __shared__ float4 s_conf4[8];
    __shared__ int    s_catcol;

    int tid  = threadIdx.x;
    int warp = tid >> 5;
    int lane = tid & 31;

    // ================= phase 0: zero (blocks 1..887) || setup (block 0) ======
    if (blockIdx.x != 0) {
        const int total = NUM_SEG * N_ARY / 4;         // 800,000 float4
        float4 z = make_float4(0.f, 0.f, 0.f, 0.f);
        for (int i = (int)(blockIdx.x - 1) * 256 + tid; i < total;
             i += (GRID_SZ - 1) * 256)
            reinterpret_cast<float4*>(g_agg)[i] = z;
    } else if (warp == 0) {
        // --- categorical softmax + top-1 (int-key argmax) ---
        float cv = (lane < NUM_CAT) ? cat_mask[lane] : -1e30f;
        float cm = cv;
        for (int o = 16; o; o >>= 1) cm = fmaxf(cm, __shfl_xor_sync(FULL, cm, o));
        float ce = (lane < NUM_CAT) ? expf(cv - cm) : 0.f;
        float cs = ce;
        for (int o = 16; o; o >>= 1) cs += __shfl_xor_sync(FULL, cs, o);
        float cp = ce / cs;
        unsigned long long ck = ((unsigned long long)__float_as_uint(cp) << 32)
                              | (unsigned)(0xFFFFFFFFu - lane);
        for (int o = 16; o; o >>= 1) {
            unsigned long long ok = __shfl_xor_sync(FULL, ck, o);
            ck = (ok > ck) ? ok : ck;
        }
        float top_cat_val = __uint_as_float((unsigned)(ck >> 32));
        if (lane == 0) g_catcol = (int)(0xFFFFFFFFu - (unsigned)ck);

        // --- numeric softmax (lane holds cols lane+32j) ---
        float nv[4];
#pragma unroll
        for (int j = 0; j < 4; j++) nv[j] = num_mask[lane + 32 * j];
        float nm = fmaxf(fmaxf(nv[0], nv[1]), fmaxf(nv[2], nv[3]));
        for (int o = 16; o; o >>= 1) nm = fmaxf(nm, __shfl_xor_sync(FULL, nm, o));
        float ns = 0.f;
#pragma unroll
        for (int j = 0; j < 4; j++) { nv[j] = expf(nv[j] - nm); ns += nv[j]; }
        for (int o = 16; o; o >>= 1) ns += __shfl_xor_sync(FULL, ns, o);
        float inv = 1.f / ns;
#pragma unroll
        for (int j = 0; j < 4; j++) nv[j] *= inv;

        // --- 64-bit sortable keys; rank = count of strictly-greater keys ---
        unsigned long long k[4];
#pragma unroll
        for (int j = 0; j < 4; j++)
            k[j] = ((unsigned long long)__float_as_uint(nv[j]) << 32)
                 | (unsigned)(0xFFFFFFFFu - (lane + 32 * j));
        int rk[4] = {0, 0, 0, 0};
        for (int s = 0; s < 32; s++) {
#pragma unroll
            for (int j2 = 0; j2 < 4; j2++) {
                unsigned long long ok = __shfl_sync(FULL, k[j2], s);
#pragma unroll
                for (int j = 0; j < 4; j++) rk[j] += (ok > k[j]);
            }
        }
#pragma unroll
        for (int j = 0; j < 4; j++) {
            if (rk[j] < N_ARY) {                  // this value is output rank rk[j]
                g_conf[rk[j]]      = 0.5f * (nv[j] + top_cat_val);
                g_cols_rank[rk[j]] = lane + 32 * j;
            }
        }
    }

    grid_bar();                                        // zero + setup visible

    // ---- per-block constants into smem (once per launch) ----
    if (tid < N_ARY)  s_cols[tid] = g_cols_rank[tid];
    if (tid < 8)      s_conf4[tid] = reinterpret_cast<const float4*>(g_conf)[tid];
    if (tid == N_ARY) s_catcol = g_catcol;
    __syncthreads();

    // ================= phase 1: scatter-add (R13-proven body) ================
    {
        int j = lane >> 3;                             // row within the 4-group
        int g = lane & 7;                              // rank-quad owner
        int c0 = s_cols[4 * g + 0];
        int c1 = s_cols[4 * g + 1];
        int c2 = s_cols[4 * g + 2];
        int c3 = s_cols[4 * g + 3];
        int catcol = s_catcol;

        for (int tile = blockIdx.x; tile < SCAT_TILES; tile += GRID_SZ) {
            int base = (tile * 8 + warp) * 4;          // 4 rows per warp
            int r    = base + j;

            int seg = __ldg(&idx_inputs[(size_t)r * NUM_CAT + catcol]);
            float4 v[4];
#pragma unroll
            for (int q = 0; q < 4; q++) {
                v[q] = __ldcs(reinterpret_cast<const float4*>(
                           inputs + (size_t)(base + q) * NUM_ATTR + NUM_CAT) + lane);
            }
#pragma unroll
            for (int q = 0; q < 4; q++)
                *reinterpret_cast<float4*>(&s_row[warp][q][lane * 4]) = v[q];
            __syncwarp();

            seg = min(max(seg, 0), NUM_SEG - 1);       // defensive: never OOB
            if (g == 0) g_catidx[r] = seg;             // compact copy for gather

            const float* srow = s_row[warp][j];
            float v0 = srow[c0], v1 = srow[c1], v2 = srow[c2], v3 = srow[c3];
            float* dst = &g_agg[(size_t)seg * N_ARY + 4 * g];
            asm volatile("red.global.add.v4.f32 [%0], {%1,%2,%3,%4};"
                         :: "l"(dst), "f"(v0), "f"(v1), "f"(v2), "f"(v3)
                         : "memory");
            __syncwarp();                              // s_row reuse next tile
        }
    }

    grid_bar();                                        // all atomics complete

    // ================= phase 2: gather + scale, float4 path ==================
    {
        int q  = lane & 7;                             // float4 index within row
        int jr = lane >> 3;                            // row within step-quad
        float4 conf4 = s_conf4[q];

        for (int tile = blockIdx.x; tile < GATH_TILES; tile += GRID_SZ) {
            int base = (tile * 8 + warp) * 16;         // 16 rows per warp
            if (base >= N_ROWS) continue;              // tail warps

            int segs[4];
#pragma unroll
            for (int s = 0; s < 4; s++)
                segs[s] = g_catidx[base + s * 4 + jr];

            float4 v[4];
#pragma unroll
            for (int s = 0; s < 4; s++)
                v[s] = reinterpret_cast<const float4*>(g_agg)[(size_t)segs[s] * 8 + q];

#pragma unroll
            for (int s = 0; s < 4; s++) {
                int r = base + s * 4 + jr;
                float4 o = make_float4(v[s].x * conf4.x, v[s].y * conf4.y,
                                       v[s].z * conf4.z, v[s].w * conf4.w);
                reinterpret_cast<float4*>(out)[(size_t)r * 8 + q] = o;
            }
        }
    }
}

// ---------------------------------------------------------------------------
extern "C" void kernel_launch(void* const* d_in, const int* in_sizes, int n_in,
                              void* d_out, int out_size) {
    const float* inputs     = (const float*)d_in[0];
    const int*   idx_inputs = (const int*)d_in[1];     // int32 (JAX x64 off)
    const float* cat_mask   = (const float*)d_in[2];
    const float* num_mask   = (const float*)d_in[3];
    float*       out        = (float*)d_out;

    k_fused<<<GRID_SZ, 256>>>(inputs, idx_inputs, cat_mask, num_mask, out);
}